// round 1
// baseline (speedup 1.0000x reference)
#include <cuda_runtime.h>
#include <cuda_bf16.h>

// Polyphase resample up=3, down=2, F=1023 taps (341 per phase).
// out[j] = 3 * sum_q h[p+3q] * x[i0 - q],  p=(511+2j)%3, i0=(511+2j-p)/3
// Per phase p (j = jp + 3k): y_p[k] = sum_q (3*h[p+3q]) * x[c_p + 2k - q]
//   jp = {1,0,2}[p],  c_p = {171,170,171}[p],  k in [0, out_len/3)

constexpr int NTAP3    = 341;    // taps per phase (1023/3)
constexpr int KTILE    = 1024;   // k-values per phase per block
constexpr int NTHREADS = 192;    // 6 warps: 2 per phase
constexpr int R        = 8;      // f32x2 accumulators per thread (16 outputs)
constexpr int WIN      = 2 * KTILE + 340;           // 2388 floats of x per block
constexpr int XSK      = WIN + (WIN >> 5) + 8;      // skewed smem size

__device__ __forceinline__ int ss(int i) { return i + (i >> 5); }  // bank skew

// pack (x[e], x[e+16]) into one 64-bit f32x2 register
__device__ __forceinline__ unsigned long long pk2(const float* __restrict__ xs, int e) {
    float lo = xs[ss(e)];
    float hi = xs[ss(e + 16)];
    unsigned long long r;
    asm("mov.b64 %0, {%1, %2};" : "=l"(r) : "f"(lo), "f"(hi));
    return r;
}

__device__ __forceinline__ void fma2(unsigned long long& d,
                                     unsigned long long a,
                                     unsigned long long b) {
    asm("fma.rn.f32x2 %0, %1, %2, %0;" : "+l"(d) : "l"(a), "l"(b));
}

__global__ void __launch_bounds__(NTHREADS, 4)
resample_poly_kernel(const float* __restrict__ x, const float* __restrict__ h,
                     float* __restrict__ out, int N, int ktotal)
{
    __shared__ float  xs[XSK];
    __shared__ float2 hdup[3 * NTAP3];

    const int tid = threadIdx.x;
    const int K0  = blockIdx.x * KTILE;
    const int ws  = 2 * K0 - 170;          // global x index of window start

    // Load x window (zero-padded out of range), bank-skewed.
    for (int i = tid; i < WIN; i += NTHREADS) {
        int g = ws + i;
        xs[ss(i)] = (g >= 0 && g < N) ? x[g] : 0.0f;
    }
    // Duplicated per-phase taps, scaled by 3 (the upsampling gain).
    for (int m = tid; m < 3 * NTAP3; m += NTHREADS) {
        int p = m % 3, q = m / 3;
        float v = 3.0f * h[m];
        hdup[p * NTAP3 + q] = make_float2(v, v);
    }
    __syncthreads();

    const int wid  = tid >> 5;
    const int lane = tid & 31;
    const int p    = wid >> 1;                       // phase 0..2 (2 warps each)
    const int tip  = ((wid & 1) << 5) | lane;        // 0..63 within phase
    const int cp   = (p == 1) ? 170 : 171;
    const int b    = cp + 170 + 32 * tip;            // local base index in xs
    const int jp   = (p == 0) ? 1 : ((p == 1) ? 0 : 2);
    const int kt   = K0 + 16 * tip;                  // first k of this thread

    unsigned long long acc[R], PA[R], PB[R];
    #pragma unroll
    for (int r = 0; r < R; ++r) acc[r] = 0ull;
    // Even-q parity chain window (q=0): elements e = b + 2r, slot r
    #pragma unroll
    for (int r = 0; r < R; ++r) PA[r] = pk2(xs, b + 2 * r);
    // Odd-q parity chain window (q=1): elements e = b - 1 + 2r, slot r
    #pragma unroll
    for (int r = 0; r < R; ++r) PB[r] = pk2(xs, b - 1 + 2 * r);

    const unsigned long long* hq =
        reinterpret_cast<const unsigned long long*>(hdup + p * NTAP3);

    // Main loop: taps 0..335 in chunks of 16 (8 even/odd pairs) so all
    // rotating-window slot indices are compile-time constants mod 8.
    for (int qo = 0; qo < 336; qo += 16) {
        #pragma unroll
        for (int qp = 0; qp < 8; ++qp) {
            const int q = qo + 2 * qp;
            unsigned long long hhA = hq[q];            // LDS.64 broadcast
            #pragma unroll
            for (int r = 0; r < R; ++r) fma2(acc[r], PA[(r - qp) & 7], hhA);
            PA[(7 - qp) & 7] = pk2(xs, b - q - 2);     // refill for q+2
            unsigned long long hhB = hq[q + 1];
            #pragma unroll
            for (int r = 0; r < R; ++r) fma2(acc[r], PB[(r - qp) & 7], hhB);
            PB[(7 - qp) & 7] = pk2(xs, b - q - 3);     // refill for q+3
        }
    }
    // Tail taps 336..340 (fresh packs; e >= b-340 >= 0 always since b >= 340).
    #pragma unroll
    for (int q = 336; q < 341; ++q) {
        unsigned long long hh = hq[q];
        #pragma unroll
        for (int r = 0; r < R; ++r) {
            unsigned long long px = pk2(xs, b - q + 2 * r);
            fma2(acc[r], px, hh);
        }
    }

    // acc[r] = (y_p[kt + r], y_p[kt + r + 8]) -> out[jp + 3k]
    #pragma unroll
    for (int r = 0; r < R; ++r) {
        float lo, hi;
        asm("mov.b64 {%0, %1}, %2;" : "=f"(lo), "=f"(hi) : "l"(acc[r]));
        int klo = kt + r, khi = kt + r + 8;
        if (klo < ktotal) out[jp + 3 * klo] = lo;
        if (khi < ktotal) out[jp + 3 * khi] = hi;
    }
}

extern "C" void kernel_launch(void* const* d_in, const int* in_sizes, int n_in,
                              void* d_out, int out_size) {
    const float* x = (const float*)d_in[0];
    const float* h = (const float*)d_in[n_in - 1];  // filter_coeffs is last input
    float* out     = (float*)d_out;
    int N          = in_sizes[0];
    int ktotal     = (out_size + 2) / 3;            // outputs per phase
    int blocks     = (ktotal + KTILE - 1) / KTILE;  // 4096 for this problem
    resample_poly_kernel<<<blocks, NTHREADS>>>(x, h, out, N, ktotal);
}

// round 3
// speedup vs baseline: 1.0767x; 1.0767x over previous
#include <cuda_runtime.h>
#include <cuda_bf16.h>

// Polyphase resample up=3, down=2, F=1023 taps (341 per phase).
// Per phase p (out[j], j = jp + 3k): y_p[k] = sum_q (3*h[p+3q]) * x[c_p + 2k - q]
//   jp = {1,0,2}[p],  c_p = {171,170,171}[p]
//
// f32x2 FMA: each thread computes 16 outputs as 8 packed accumulators pairing
// (k+r, k+r+8). Pack (x[e], x[e+16]) slides by -1 per tap -> two parity-chained
// rotating register windows (even/odd q). Packs are PRE-PAIRED in smem so each
// refill is a single conflict-free LDS.64. Filter loads are software-pipelined
// 2 iterations deep to hide the 29-cycle LDS latency.

constexpr int NTAP3    = 341;    // taps per phase
constexpr int KTILE    = 1024;   // k-values per phase per block
constexpr int NTHREADS = 192;    // 6 warps: 2 per phase
constexpr int R        = 8;      // f32x2 accumulators per thread (16 outputs)
constexpr int WIN      = 2 * KTILE + 340;        // 2388 x-samples per block
constexpr int PXN      = WIN - 16;               // pairs (i, i+16), i in [0, PXN)
constexpr int PXSK     = PXN + (PXN >> 5) + 4;   // skewed pair-array size

typedef unsigned long long ull;

__device__ __forceinline__ int ps(int i) { return i + (i >> 5); }  // pair skew

__device__ __forceinline__ ull ldpx(const float2* __restrict__ px, int i) {
    return *reinterpret_cast<const ull*>(px + ps(i));
}

__device__ __forceinline__ void fma2(ull& d, ull a, ull b) {
    asm("fma.rn.f32x2 %0, %1, %2, %0;" : "+l"(d) : "l"(a), "l"(b));
}

__global__ void __launch_bounds__(NTHREADS, 4)
resample_poly_kernel(const float* __restrict__ x, const float* __restrict__ h,
                     float* __restrict__ out, int N, int ktotal)
{
    __shared__ float2 px[PXSK];          // pre-paired x window
    __shared__ float2 hdup[3 * NTAP3];   // duplicated (v,v) taps per phase

    const int tid = threadIdx.x;
    const int K0  = blockIdx.x * KTILE;
    const int ws  = 2 * K0 - 170;        // global x index of window start

    // Build pre-paired window: px[i] = (x[ws+i], x[ws+i+16]), zero-padded.
    for (int i = tid; i < PXN; i += NTHREADS) {
        int g  = ws + i;
        int g2 = g + 16;
        float lo = (g  >= 0 && g  < N) ? x[g]  : 0.0f;
        float hi = (g2 >= 0 && g2 < N) ? x[g2] : 0.0f;
        px[ps(i)] = make_float2(lo, hi);
    }
    // Duplicated per-phase taps, scaled by 3 (upsampling gain).
    for (int m = tid; m < 3 * NTAP3; m += NTHREADS) {
        int p = m % 3, q = m / 3;
        float v = 3.0f * h[m];
        hdup[p * NTAP3 + q] = make_float2(v, v);
    }
    __syncthreads();

    const int wid  = tid >> 5;
    const int lane = tid & 31;
    const int p    = wid >> 1;                    // phase 0..2 (2 warps each)
    const int tip  = ((wid & 1) << 5) | lane;     // 0..63 within phase
    const int cp   = (p == 1) ? 170 : 171;
    const int b    = cp + 170 + 32 * tip;         // local base index
    const int jp   = (p == 0) ? 1 : ((p == 1) ? 0 : 2);
    const int kt   = K0 + 16 * tip;               // first k of this thread

    ull acc[R], PA[R], PB[R];
    #pragma unroll
    for (int r = 0; r < R; ++r) acc[r] = 0ull;
    #pragma unroll
    for (int r = 0; r < R; ++r) PA[r] = ldpx(px, b + 2 * r);       // q=0 chain
    #pragma unroll
    for (int r = 0; r < R; ++r) PB[r] = ldpx(px, b - 1 + 2 * r);   // q=1 chain

    const ull* hq = reinterpret_cast<const ull*>(hdup + p * NTAP3);

    // Software-pipelined filter registers (distance 2 tap-pairs ahead).
    ull hA  = hq[0], hB  = hq[1];
    ull hA2 = hq[2], hB2 = hq[3];

    // Main loop: taps 0..335 in chunks of 16 (rotating slots compile-time mod 8).
    for (int qo = 0; qo < 336; qo += 16) {
        #pragma unroll
        for (int qp = 0; qp < 8; ++qp) {
            const int q = qo + 2 * qp;
            // Prefetch taps q+4, q+5 (q <= 334 -> q+5 <= 339 < 341).
            ull hA3 = hq[q + 4];
            ull hB3 = hq[q + 5];
            #pragma unroll
            for (int r = 0; r < R; ++r) fma2(acc[r], PA[(r - qp) & 7], hA);
            PA[(7 - qp) & 7] = ldpx(px, b - q - 2);   // refill for tap q+2
            #pragma unroll
            for (int r = 0; r < R; ++r) fma2(acc[r], PB[(r - qp) & 7], hB);
            PB[(7 - qp) & 7] = ldpx(px, b - q - 3);   // refill for tap q+3
            hA = hA2; hB = hB2; hA2 = hA3; hB2 = hB3;
        }
    }
    // Tail taps 336..340 (b >= 340, so all pair indices >= 0).
    #pragma unroll
    for (int q = 336; q < 341; ++q) {
        ull hh = hq[q];
        #pragma unroll
        for (int r = 0; r < R; ++r) {
            ull pxx = ldpx(px, b - q + 2 * r);
            fma2(acc[r], pxx, hh);
        }
    }

    // acc[r] = (y_p[kt+r], y_p[kt+r+8]) -> out[jp + 3k]
    #pragma unroll
    for (int r = 0; r < R; ++r) {
        float lo, hi;
        asm("mov.b64 {%0, %1}, %2;" : "=f"(lo), "=f"(hi) : "l"(acc[r]));
        int klo = kt + r, khi = kt + r + 8;
        if (klo < ktotal) out[jp + 3 * klo] = lo;
        if (khi < ktotal) out[jp + 3 * khi] = hi;
    }
}

extern "C" void kernel_launch(void* const* d_in, const int* in_sizes, int n_in,
                              void* d_out, int out_size) {
    const float* x = (const float*)d_in[0];
    const float* h = (const float*)d_in[n_in - 1];
    float* out     = (float*)d_out;
    int N          = in_sizes[0];
    int ktotal     = (out_size + 2) / 3;
    int blocks     = (ktotal + KTILE - 1) / KTILE;
    resample_poly_kernel<<<blocks, NTHREADS>>>(x, h, out, N, ktotal);
}